// round 2
// baseline (speedup 1.0000x reference)
#include <cuda_runtime.h>

#define NN 50000
#define EE 800000
#define HH 64
#define RR 4
#define CC 4
#define GG 512

// ---------------- device scratch (static, no allocation) ----------------
__device__ float g_W1[64 * 320];                    // packed [k][r*64+o | root]
__device__ float g_W2[64 * 320];
__device__ float g_h[(size_t)RR * NN * HH];         // per-relation transformed nodes
__device__ float g_self[(size_t)NN * HH];           // root transform + bias
__device__ float g_agg[(size_t)RR * NN * HH];       // per-relation scatter sums
__device__ float g_cnt[RR * NN];                    // per-relation in-degree
__device__ float g_x2[(size_t)NN * HH];             // layer-1 output
__device__ float g_pool[GG * HH];                   // graph pooling sums
__device__ float g_pcnt[GG];                        // nodes per graph

// ---------------- weight preparation: W[r] = sum_b comp[r,b]*basis[b], + root --------
__global__ void prep_w(const float* __restrict__ b1, const float* __restrict__ c1,
                       const float* __restrict__ r1, const float* __restrict__ b2,
                       const float* __restrict__ c2, const float* __restrict__ r2) {
    int t = blockIdx.x * blockDim.x + threadIdx.x;
    if (t >= 2 * 64 * 320) return;
    int layer = t / 20480;
    int i = t % 20480;
    int k = i / 320;
    int c = i % 320;
    const float* basis = layer ? b2 : b1;
    const float* comp  = layer ? c2 : c1;
    const float* root  = layer ? r2 : r1;
    float v;
    if (c < 256) {
        int r = c >> 6, o = c & 63;
        v = 0.f;
#pragma unroll
        for (int b = 0; b < 4; b++)
            v += comp[r * 4 + b] * basis[((size_t)b * 64 + k) * 64 + o];
    } else {
        v = root[k * 64 + (c - 256)];
    }
    (layer ? g_W2 : g_W1)[k * 320 + c] = v;
}

// ---------------- zero the accumulated scratch (runs inside the graph) ----------------
__global__ void zero_scratch() {
    size_t t = (size_t)blockIdx.x * blockDim.x + threadIdx.x;
    size_t stride = (size_t)gridDim.x * blockDim.x;
    size_t n4 = (size_t)RR * NN * HH / 4;
    float4 z = make_float4(0.f, 0.f, 0.f, 0.f);
    for (size_t i = t; i < n4; i += stride) ((float4*)g_agg)[i] = z;
    for (size_t i = t; i < (size_t)RR * NN; i += stride) g_cnt[i] = 0.f;
    for (size_t i = t; i < (size_t)GG * HH; i += stride) g_pool[i] = 0.f;
    for (size_t i = t; i < (size_t)GG; i += stride) g_pcnt[i] = 0.f;
}

// ---------------- SGEMM: [N,64] @ [64,320] -> g_h (4 relations) + g_self --------------
// 64x64 tile per block, 256 threads, 4x4 microtile, full K=64 in one shot.
__global__ void gemm64(const float* __restrict__ Xin, const float* __restrict__ bias,
                       int layer) {
    __shared__ float As[64 * 68];   // transposed: As[k][m], lda 68 keeps 16B alignment
    __shared__ float Bs[64 * 64];   // Bs[k][c]
    const float* X = layer ? g_x2 : Xin;
    const float* W = layer ? g_W2 : g_W1;

    int t = threadIdx.x;
    int nodeBase = blockIdx.x * 64;
    int colTile = blockIdx.y;   // 0..3 = relation r, 4 = root/self

#pragma unroll
    for (int i = 0; i < 4; i++) {
        int f = t + i * 256;            // 0..1023
        int row = f >> 4;
        int k4 = (f & 15) << 2;
        int gn = nodeBase + row;
        float4 v = make_float4(0.f, 0.f, 0.f, 0.f);
        if (gn < NN) v = *(const float4*)(X + (size_t)gn * 64 + k4);
        As[(k4 + 0) * 68 + row] = v.x;
        As[(k4 + 1) * 68 + row] = v.y;
        As[(k4 + 2) * 68 + row] = v.z;
        As[(k4 + 3) * 68 + row] = v.w;
        // B tile: same index decomposition
        int k = f >> 4;
        int c4 = (f & 15) << 2;
        *(float4*)&Bs[k * 64 + c4] =
            *(const float4*)(W + (size_t)k * 320 + colTile * 64 + c4);
    }
    __syncthreads();

    int tx = t & 15, ty = t >> 4;
    float acc[4][4];
#pragma unroll
    for (int i = 0; i < 4; i++)
#pragma unroll
        for (int j = 0; j < 4; j++) acc[i][j] = 0.f;

#pragma unroll
    for (int k = 0; k < 64; k++) {
        float4 a = *(const float4*)&As[k * 68 + ty * 4];
        float4 b = *(const float4*)&Bs[k * 64 + tx * 4];
        float av[4] = {a.x, a.y, a.z, a.w};
        float bv[4] = {b.x, b.y, b.z, b.w};
#pragma unroll
        for (int i = 0; i < 4; i++)
#pragma unroll
            for (int j = 0; j < 4; j++) acc[i][j] += av[i] * bv[j];
    }

    float4 bv4 = make_float4(0.f, 0.f, 0.f, 0.f);
    if (colTile == 4) bv4 = *(const float4*)(bias + tx * 4);

#pragma unroll
    for (int i = 0; i < 4; i++) {
        int gn = nodeBase + ty * 4 + i;
        if (gn >= NN) continue;
        float* dst = (colTile < 4)
                         ? (g_h + ((size_t)colTile * NN + gn) * 64 + tx * 4)
                         : (g_self + (size_t)gn * 64 + tx * 4);
        float4 o = make_float4(acc[i][0] + bv4.x, acc[i][1] + bv4.y,
                               acc[i][2] + bv4.z, acc[i][3] + bv4.w);
        *(float4*)dst = o;
    }
}

// ---------------- edge gather + vector-atomic scatter ----------------
// 16 lanes per edge, one float4 each. Gathers hit L2 (h tables = 51MB < 126MB L2).
__global__ void edge_msg(const int* __restrict__ src, const int* __restrict__ dst,
                         const int* __restrict__ et) {
    int gt = blockIdx.x * blockDim.x + threadIdx.x;
    int e = gt >> 4;
    if (e >= EE) return;
    int j = gt & 15;
    int r = et[e], s = src[e], d = dst[e];
    float4 v = *(const float4*)(g_h + ((size_t)r * NN + s) * 64 + j * 4);
    float* a = g_agg + ((size_t)r * NN + d) * 64 + (size_t)j * 4;
    asm volatile("red.global.add.v4.f32 [%0], {%1,%2,%3,%4};"
                 :: "l"(a), "f"(v.x), "f"(v.y), "f"(v.z), "f"(v.w) : "memory");
    if (j == 0) atomicAdd(&g_cnt[r * NN + d], 1.0f);
}

// ---------------- combine: self + sum_r agg/max(cnt,1), relu; layer1 also pools ------
__global__ void combine(const int* __restrict__ batch, int layer) {
    int t = blockIdx.x * blockDim.x + threadIdx.x;
    int n = t >> 4;
    if (n >= NN) return;
    int j = t & 15;
    float4 o = *(const float4*)(g_self + (size_t)n * 64 + j * 4);
#pragma unroll
    for (int r = 0; r < 4; r++) {
        float cn = g_cnt[r * NN + n];
        float inv = 1.f / fmaxf(cn, 1.f);
        float4 a = *(const float4*)(g_agg + ((size_t)r * NN + n) * 64 + j * 4);
        o.x += a.x * inv; o.y += a.y * inv; o.z += a.z * inv; o.w += a.w * inv;
    }
    o.x = fmaxf(o.x, 0.f); o.y = fmaxf(o.y, 0.f);
    o.z = fmaxf(o.z, 0.f); o.w = fmaxf(o.w, 0.f);
    if (layer == 0) {
        *(float4*)(g_x2 + (size_t)n * 64 + j * 4) = o;
    } else {
        int g = batch[n];
        float* p = g_pool + g * 64 + j * 4;
        asm volatile("red.global.add.v4.f32 [%0], {%1,%2,%3,%4};"
                     :: "l"(p), "f"(o.x), "f"(o.y), "f"(o.z), "f"(o.w) : "memory");
        if (j == 0) atomicAdd(&g_pcnt[g], 1.0f);
    }
}

// ---------------- classifier: (pool/cnt) @ [64,4] + bias -> [512,4] ----------------
__global__ void classify(const float* __restrict__ w, const float* __restrict__ b,
                         float* __restrict__ out) {
    int t = blockIdx.x * blockDim.x + threadIdx.x;
    if (t >= GG * CC) return;
    int g = t / CC, c = t % CC;
    float inv = 1.f / fmaxf(g_pcnt[g], 1.f);
    float acc = b[c];
#pragma unroll
    for (int k = 0; k < 64; k++)
        acc += g_pool[g * 64 + k] * inv * w[k * CC + c];
    out[t] = acc;
}

// ---------------- launch ----------------
extern "C" void kernel_launch(void* const* d_in, const int* in_sizes, int n_in,
                              void* d_out, int out_size) {
    const float* x      = (const float*)d_in[0];
    const int*   ei     = (const int*)d_in[1];
    const int*   et     = (const int*)d_in[2];
    const int*   batch  = (const int*)d_in[3];
    const float* basis1 = (const float*)d_in[4];
    const float* comp1  = (const float*)d_in[5];
    const float* root1  = (const float*)d_in[6];
    const float* bias1  = (const float*)d_in[7];
    const float* basis2 = (const float*)d_in[8];
    const float* comp2  = (const float*)d_in[9];
    const float* root2  = (const float*)d_in[10];
    const float* bias2  = (const float*)d_in[11];
    const float* clw    = (const float*)d_in[12];
    const float* clb    = (const float*)d_in[13];
    float* out = (float*)d_out;

    const int* src = ei;        // edge_index[0]
    const int* dstp = ei + EE;  // edge_index[1]

    dim3 ggrid((NN + 63) / 64, 5);

    prep_w<<<160, 256>>>(basis1, comp1, root1, basis2, comp2, root2);

    // ---- layer 1 ----
    zero_scratch<<<1024, 256>>>();
    gemm64<<<ggrid, 256>>>(x, bias1, 0);
    edge_msg<<<(EE * 16) / 256, 256>>>(src, dstp, et);   // exactly 50000 blocks
    combine<<<(NN * 16) / 256, 256>>>(batch, 0);         // exactly 3125 blocks

    // ---- layer 2 ----
    zero_scratch<<<1024, 256>>>();
    gemm64<<<ggrid, 256>>>(x, bias2, 1);
    edge_msg<<<(EE * 16) / 256, 256>>>(src, dstp, et);
    combine<<<(NN * 16) / 256, 256>>>(batch, 1);

    // ---- pooled classifier ----
    classify<<<(GG * CC + 255) / 256, 256>>>(clw, clb, out);
}

// round 3
// speedup vs baseline: 1.1279x; 1.1279x over previous
#include <cuda_runtime.h>

#define NN 50000
#define EE 800000
#define RR 4
#define CC 4
#define GG 512

// ---------------- device scratch (static, no allocation) ----------------
__device__ float g_W1[64 * 384];                    // [k][c], c: 0-255 rel, 256-319 root, 320-383 zero pad
__device__ float g_W2[64 * 384];
__device__ float g_h[(size_t)RR * NN * 64];         // per-relation transformed nodes
__device__ float g_agg1[(size_t)NN * 64];           // layer1: self+bias, then += scaled messages
__device__ float g_agg2[(size_t)NN * 64];
__device__ float g_cnt[RR * NN];
__device__ float g_inv[RR * NN];
__device__ float g_pool[GG * 64];
__device__ float g_pcnt[GG];

// ---------------- weight prep: W[k][r*64+o] = sum_b comp[r,b]*basis[b][k][o]; root; pad --
__global__ void prep_w(const float* __restrict__ b1, const float* __restrict__ c1,
                       const float* __restrict__ r1, const float* __restrict__ b2,
                       const float* __restrict__ c2, const float* __restrict__ r2) {
    int t = blockIdx.x * blockDim.x + threadIdx.x;
    if (t >= 2 * 64 * 384) return;
    int layer = t / 24576;
    int i = t % 24576;
    int k = i / 384;
    int c = i % 384;
    const float* basis = layer ? b2 : b1;
    const float* comp  = layer ? c2 : c1;
    const float* root  = layer ? r2 : r1;
    float v = 0.f;
    if (c < 256) {
        int r = c >> 6, o = c & 63;
#pragma unroll
        for (int b = 0; b < 4; b++)
            v += comp[r * 4 + b] * basis[((size_t)b * 64 + k) * 64 + o];
    } else if (c < 320) {
        v = root[k * 64 + (c - 256)];
    }
    (layer ? g_W2 : g_W1)[k * 384 + c] = v;
}

// ---------------- zero the small accumulators ----------------
__global__ void zero_small() {
    int t = blockIdx.x * blockDim.x + threadIdx.x;
    int stride = gridDim.x * blockDim.x;
    for (int i = t; i < RR * NN; i += stride) g_cnt[i] = 0.f;
    for (int i = t; i < GG * 64; i += stride) g_pool[i] = 0.f;
    for (int i = t; i < GG; i += stride) g_pcnt[i] = 0.f;
}

// ---------------- count edges per (relation, dst); then invert ----------------
__global__ void count_edges(const int* __restrict__ dst, const int* __restrict__ et) {
    int e = blockIdx.x * blockDim.x + threadIdx.x;
    if (e >= EE) return;
    atomicAdd(&g_cnt[et[e] * NN + dst[e]], 1.0f);
}

__global__ void invert_cnt() {
    int i = blockIdx.x * blockDim.x + threadIdx.x;
    if (i < RR * NN) g_inv[i] = 1.0f / fmaxf(g_cnt[i], 1.0f);
}

// ---------------- SGEMM: [N,64] @ [64,384] with 8x8 microtile -----------------
// 128-row x 128-col tiles, 256 threads. colTile 0,1: relations; colTile 2: self
// (cols 256-319) + zero pad. Self tile initializes agg with +bias.
// As transposed [64][132], Bs [64][132] in dynamic smem.
#define AS_PAD 132
__global__ void __launch_bounds__(256)
gemm128(const float* __restrict__ Xin, const float* __restrict__ bias, int layer) {
    extern __shared__ float smem[];
    float* As = smem;                 // [64][132]  As[k][m]
    float* Bs = smem + 64 * AS_PAD;   // [64][132]  Bs[k][c]
    const float* X = layer ? g_agg1 : Xin;
    const float* W = layer ? g_W2 : g_W1;
    float* aggOut = layer ? g_agg2 : g_agg1;
    const bool doRelu = (layer == 1);

    int t = threadIdx.x;
    int nodeBase = blockIdx.x * 128;
    int colTile = blockIdx.y;         // 0,1,2

    // load A tile: 128 rows x 64 k, transposed into As[k][row]
#pragma unroll
    for (int i = 0; i < 8; i++) {
        int f = t + i * 256;          // 0..2047
        int row = f >> 4;
        int k4 = (f & 15) << 2;
        int gn = nodeBase + row;
        float4 v = make_float4(0.f, 0.f, 0.f, 0.f);
        if (gn < NN) v = *(const float4*)(X + (size_t)gn * 64 + k4);
        if (doRelu) {
            v.x = fmaxf(v.x, 0.f); v.y = fmaxf(v.y, 0.f);
            v.z = fmaxf(v.z, 0.f); v.w = fmaxf(v.w, 0.f);
        }
        As[(k4 + 0) * AS_PAD + row] = v.x;
        As[(k4 + 1) * AS_PAD + row] = v.y;
        As[(k4 + 2) * AS_PAD + row] = v.z;
        As[(k4 + 3) * AS_PAD + row] = v.w;
    }
    // load B tile: 64 k x 128 cols (W padded to 384 cols, no guard needed)
#pragma unroll
    for (int i = 0; i < 8; i++) {
        int f = t + i * 256;          // 0..2047
        int k = f >> 5;
        int c4 = (f & 31) << 2;
        *(float4*)&Bs[k * AS_PAD + c4] =
            *(const float4*)(W + (size_t)k * 384 + colTile * 128 + c4);
    }
    __syncthreads();

    int tx = t & 15, ty = t >> 4;     // rows: ty*4+{0..3}, 64+ty*4+{0..3}; cols likewise w/ tx
    float acc[8][8];
#pragma unroll
    for (int i = 0; i < 8; i++)
#pragma unroll
        for (int j = 0; j < 8; j++) acc[i][j] = 0.f;

#pragma unroll
    for (int k = 0; k < 64; k++) {
        float4 a0 = *(const float4*)&As[k * AS_PAD + ty * 4];
        float4 a1 = *(const float4*)&As[k * AS_PAD + 64 + ty * 4];
        float4 b0 = *(const float4*)&Bs[k * AS_PAD + tx * 4];
        float4 b1 = *(const float4*)&Bs[k * AS_PAD + 64 + tx * 4];
        float av[8] = {a0.x, a0.y, a0.z, a0.w, a1.x, a1.y, a1.z, a1.w};
        float bv[8] = {b0.x, b0.y, b0.z, b0.w, b1.x, b1.y, b1.z, b1.w};
#pragma unroll
        for (int i = 0; i < 8; i++)
#pragma unroll
            for (int j = 0; j < 8; j++) acc[i][j] += av[i] * bv[j];
    }

    float4 bv4 = make_float4(0.f, 0.f, 0.f, 0.f);
    if (colTile == 2) bv4 = *(const float4*)(bias + tx * 4);   // self half (j2=0)

#pragma unroll
    for (int i = 0; i < 8; i++) {
        int gn = nodeBase + ((i < 4) ? (ty * 4 + i) : (64 + ty * 4 + i - 4));
        if (gn >= NN) continue;
#pragma unroll
        for (int j2 = 0; j2 < 2; j2++) {
            int cbase = colTile * 128 + j2 * 64 + tx * 4;
            if (cbase >= 320) continue;   // zero-pad columns
            float4 v = make_float4(acc[i][j2 * 4 + 0], acc[i][j2 * 4 + 1],
                                   acc[i][j2 * 4 + 2], acc[i][j2 * 4 + 3]);
            int r = cbase >> 6, o = cbase & 63;
            if (r < 4) {
                *(float4*)(g_h + ((size_t)r * NN + gn) * 64 + o) = v;
            } else {
                v.x += bv4.x; v.y += bv4.y; v.z += bv4.z; v.w += bv4.w;
                *(float4*)(aggOut + (size_t)gn * 64 + o) = v;
            }
        }
    }
}

// ---------------- edge gather + scaled vector-atomic scatter ----------------
// 8 lanes per edge, two independent float4 gathers per lane (MLP=2).
__global__ void edge_msg(const int* __restrict__ src, const int* __restrict__ dst,
                         const int* __restrict__ et, int layer) {
    int gt = blockIdx.x * blockDim.x + threadIdx.x;
    int e = gt >> 3;
    if (e >= EE) return;
    int j = gt & 7;
    int r = et[e], s = src[e], d = dst[e];
    float inv = g_inv[r * NN + d];
    const float* hp = g_h + ((size_t)r * NN + s) * 64 + j * 8;
    float4 v0 = *(const float4*)hp;
    float4 v1 = *(const float4*)(hp + 4);
    float* a = (layer ? g_agg2 : g_agg1) + (size_t)d * 64 + (size_t)j * 8;
    asm volatile("red.global.add.v4.f32 [%0], {%1,%2,%3,%4};"
                 :: "l"(a), "f"(v0.x * inv), "f"(v0.y * inv),
                    "f"(v0.z * inv), "f"(v0.w * inv) : "memory");
    asm volatile("red.global.add.v4.f32 [%0], {%1,%2,%3,%4};"
                 :: "l"(a + 4), "f"(v1.x * inv), "f"(v1.y * inv),
                    "f"(v1.z * inv), "f"(v1.w * inv) : "memory");
}

// ---------------- final: relu(agg2), pool per graph ----------------
__global__ void pool_final(const int* __restrict__ batch) {
    int t = blockIdx.x * blockDim.x + threadIdx.x;
    int n = t >> 4;
    if (n >= NN) return;
    int j = t & 15;
    float4 o = *(const float4*)(g_agg2 + (size_t)n * 64 + j * 4);
    o.x = fmaxf(o.x, 0.f); o.y = fmaxf(o.y, 0.f);
    o.z = fmaxf(o.z, 0.f); o.w = fmaxf(o.w, 0.f);
    int g = batch[n];
    float* p = g_pool + g * 64 + j * 4;
    asm volatile("red.global.add.v4.f32 [%0], {%1,%2,%3,%4};"
                 :: "l"(p), "f"(o.x), "f"(o.y), "f"(o.z), "f"(o.w) : "memory");
    if (j == 0) atomicAdd(&g_pcnt[g], 1.0f);
}

// ---------------- classifier: (pool/cnt) @ [64,4] + bias -> [512,4] ----------------
__global__ void classify(const float* __restrict__ w, const float* __restrict__ b,
                         float* __restrict__ out) {
    int t = blockIdx.x * blockDim.x + threadIdx.x;
    if (t >= GG * CC) return;
    int g = t / CC, c = t % CC;
    float inv = 1.f / fmaxf(g_pcnt[g], 1.f);
    float acc = b[c];
#pragma unroll
    for (int k = 0; k < 64; k++)
        acc += g_pool[g * 64 + k] * inv * w[k * CC + c];
    out[t] = acc;
}

// ---------------- launch ----------------
extern "C" void kernel_launch(void* const* d_in, const int* in_sizes, int n_in,
                              void* d_out, int out_size) {
    const float* x      = (const float*)d_in[0];
    const int*   ei     = (const int*)d_in[1];
    const int*   et     = (const int*)d_in[2];
    const int*   batch  = (const int*)d_in[3];
    const float* basis1 = (const float*)d_in[4];
    const float* comp1  = (const float*)d_in[5];
    const float* root1  = (const float*)d_in[6];
    const float* bias1  = (const float*)d_in[7];
    const float* basis2 = (const float*)d_in[8];
    const float* comp2  = (const float*)d_in[9];
    const float* root2  = (const float*)d_in[10];
    const float* bias2  = (const float*)d_in[11];
    const float* clw    = (const float*)d_in[12];
    const float* clb    = (const float*)d_in[13];
    float* out = (float*)d_out;

    const int* src = ei;        // edge_index[0]
    const int* dstp = ei + EE;  // edge_index[1]

    static int smem_set = 0;
    const int GEMM_SMEM = 2 * 64 * AS_PAD * sizeof(float);   // 67584 B
    if (!smem_set) {
        cudaFuncSetAttribute(gemm128, cudaFuncAttributeMaxDynamicSharedMemorySize,
                             GEMM_SMEM);
        smem_set = 1;
    }

    dim3 ggrid((NN + 127) / 128, 3);

    zero_small<<<256, 256>>>();
    prep_w<<<192, 256>>>(basis1, comp1, root1, basis2, comp2, root2);
    count_edges<<<EE / 256, 256>>>(dstp, et);
    invert_cnt<<<(RR * NN + 255) / 256, 256>>>();

    // ---- layer 1 ----
    gemm128<<<ggrid, 256, GEMM_SMEM>>>(x, bias1, 0);
    edge_msg<<<(EE * 8) / 256, 256>>>(src, dstp, et, 0);

    // ---- layer 2 ----
    gemm128<<<ggrid, 256, GEMM_SMEM>>>(x, bias2, 1);
    edge_msg<<<(EE * 8) / 256, 256>>>(src, dstp, et, 1);

    // ---- pool + classifier ----
    pool_final<<<(NN * 16) / 256, 256>>>(batch);
    classify<<<(GG * CC + 255) / 256, 256>>>(clw, clb, out);
}